// round 12
// baseline (speedup 1.0000x reference)
#include <cuda_runtime.h>
#include <cuda_bf16.h>
#include <mma.h>
#include <math.h>
#include <stdint.h>

namespace wmma = nvcuda::wmma;

#define HID 256
#define NMAX 50000
#define EMAX 800000

// ---------------- device scratch (referenced ONLY in device code) ----------
__device__ __align__(128) float g_Q[(size_t)NMAX * HID];
__device__ __align__(128) float g_K[(size_t)NMAX * HID];
__device__ __align__(128) float g_V[(size_t)NMAX * HID];
__device__ __align__(128) float g_attn[(size_t)NMAX * HID];
__device__ __align__(128) float g_h[(size_t)NMAX * HID];   // RAW out-proj

__device__ __align__(128) unsigned short g_xhi[(size_t)NMAX * HID];
__device__ __align__(128) unsigned short g_xlo[(size_t)NMAX * HID];
__device__ __align__(128) unsigned short g_ahi[(size_t)NMAX * HID];
__device__ __align__(128) unsigned short g_alo[(size_t)NMAX * HID];
__device__ __align__(128) unsigned short g_wbhi[4][HID * HID];  // W [K,N] hi
__device__ __align__(128) unsigned short g_wblo[4][HID * HID];  // W [K,N] lo

__device__ int g_cnt[NMAX + 1];
__device__ int g_rowoff[NMAX + 1];
__device__ int g_cursor[NMAX];
__device__ int g_csrc[EMAX];
__device__ int g_blksum[64];

__device__ float g_colsum[HID];
__device__ float g_colsq[HID];

// ---------------- bf16 round-to-nearest-even via bit math -------------------
__device__ __forceinline__ uint32_t f2bf(float x) {
    uint32_t b = __float_as_uint(x);
    return (b + 0x7FFFu + ((b >> 16) & 1u)) >> 16;
}
__device__ __forceinline__ float bf2f(uint32_t h) {
    return __uint_as_float(h << 16);
}

// ---------------- zero / CSR build -----------------------------------------
__global__ void zero_kernel(int n) {
    int i = blockIdx.x * blockDim.x + threadIdx.x;
    if (i <= n) g_cnt[i] = 0;
    if (i < HID) { g_colsum[i] = 0.f; g_colsq[i] = 0.f; }
}

__global__ void count_kernel(const int* __restrict__ dst, int e) {
    int i = blockIdx.x * blockDim.x + threadIdx.x;
    if (i < e) atomicAdd(&g_cnt[dst[i]], 1);
}

__global__ void scanA(int n) {
    __shared__ int sm[1024];
    int tid = threadIdx.x;
    int gid = blockIdx.x * 1024 + tid;
    int v = (gid < n) ? g_cnt[gid] : 0;
    sm[tid] = v;
    __syncthreads();
    for (int off = 1; off < 1024; off <<= 1) {
        int t = (tid >= off) ? sm[tid - off] : 0;
        __syncthreads();
        sm[tid] += t;
        __syncthreads();
    }
    if (gid < n) g_rowoff[gid] = sm[tid] - v;
    if (tid == 1023) g_blksum[blockIdx.x] = sm[1023];
}

__global__ void scanB(int nb) {
    __shared__ int sm[64];
    int tid = threadIdx.x;
    int v = (tid < nb) ? g_blksum[tid] : 0;
    sm[tid] = v;
    __syncthreads();
    for (int off = 1; off < 64; off <<= 1) {
        int t = (tid >= off) ? sm[tid - off] : 0;
        __syncthreads();
        sm[tid] += t;
        __syncthreads();
    }
    if (tid < nb) g_blksum[tid] = sm[tid] - v;
}

__global__ void scanC(int n, int e) {
    int gid = blockIdx.x * blockDim.x + threadIdx.x;
    if (gid < n) {
        int r = g_rowoff[gid] + g_blksum[gid >> 10];
        g_rowoff[gid] = r;
        g_cursor[gid] = r;
    }
    if (gid == 0) g_rowoff[n] = e;
}

__global__ void scatter_kernel(const int* __restrict__ src,
                               const int* __restrict__ dst, int e) {
    int i = blockIdx.x * blockDim.x + threadIdx.x;
    if (i < e) {
        int p = atomicAdd(&g_cursor[dst[i]], 1);
        g_csrc[p] = src[i];
    }
}

// ---------------- bf16 split conversions (device-side symbol refs) ---------
// SRC 0: xin (kernel arg) -> g_xhi/g_xlo ; SRC 1: g_attn -> g_ahi/g_alo
template <int SRC>
__global__ void conv_split(const float* __restrict__ xin, int total2) {
    int i = blockIdx.x * blockDim.x + threadIdx.x;
    if (i >= total2) return;
    const float2* src = (SRC == 0) ? (const float2*)xin : (const float2*)g_attn;
    uint32_t* hi = (SRC == 0) ? (uint32_t*)g_xhi : (uint32_t*)g_ahi;
    uint32_t* lo = (SRC == 0) ? (uint32_t*)g_xlo : (uint32_t*)g_alo;
    float2 v = src[i];
    uint32_t h0 = f2bf(v.x);
    uint32_t h1 = f2bf(v.y);
    uint32_t l0 = f2bf(v.x - bf2f(h0));
    uint32_t l1 = f2bf(v.y - bf2f(h1));
    hi[i] = h0 | (h1 << 16);
    lo[i] = l0 | (l1 << 16);
}

// split W [K,N] row-major -> g_wbhi/g_wblo[widx] (row-major, no transpose)
__global__ void conv_w(const float* __restrict__ W, int widx) {
    int idx = blockIdx.x * 256 + threadIdx.x;   // 65536 total
    float v = W[idx];
    uint32_t h = f2bf(v);
    uint32_t l = f2bf(v - bf2f(h));
    g_wbhi[widx][idx] = (unsigned short)h;
    g_wblo[widx][idx] = (unsigned short)l;
}

// ---------------- WMMA GEMM: C[M,256] = A @ W (bf16x3 split) ----------------
// CTA: 256 threads = 8 warps; CTA tile 128(M) x 64(N); warp tile 16x64.
// W chunk (64k x 64n, hi+lo) staged in 16KB static smem; A read from L2.
// MODE 0: A = x split, blockIdx.z selects W[z] -> Q/K/V
// MODE 1: A = attn split, W[3] -> g_h RAW (bias+residual folded into norm)
#define NFRAG(ACC, NF)                                                        \
    do {                                                                      \
        wmma::fragment<wmma::matrix_b, 16, 16, 16, __nv_bfloat16,             \
                       wmma::row_major> bh, bl;                               \
        wmma::load_matrix_sync(bh,                                            \
            (const __nv_bfloat16*)sBhi + ks * 1024 + (NF) * 16, 64);          \
        wmma::load_matrix_sync(bl,                                            \
            (const __nv_bfloat16*)sBlo + ks * 1024 + (NF) * 16, 64);          \
        wmma::mma_sync(ACC, ah, bh, ACC);                                     \
        wmma::mma_sync(ACC, ah, bl, ACC);                                     \
        wmma::mma_sync(ACC, al, bh, ACC);                                     \
    } while (0)

template <int MODE>
__global__ void __launch_bounds__(256)
gemm_wmma(int M) {
    __shared__ __align__(128) unsigned short sBhi[64 * 64];   // 8 KB
    __shared__ __align__(128) unsigned short sBlo[64 * 64];   // 8 KB

    int tid = threadIdx.x;
    int wid = tid >> 5;
    int m0 = blockIdx.y * 128 + wid * 16;
    int n0 = blockIdx.x * 64;

    const unsigned short *Ahi, *Alo, *Whi, *Wlo;
    float* C;
    if (MODE == 0) {
        Ahi = g_xhi; Alo = g_xlo;
        int z = blockIdx.z;
        Whi = g_wbhi[z]; Wlo = g_wblo[z];
        C = (z == 0) ? g_Q : (z == 1) ? g_K : g_V;
    } else {
        Ahi = g_ahi; Alo = g_alo;
        Whi = g_wbhi[3]; Wlo = g_wblo[3];
        C = g_h;
    }

    bool valid = (m0 < M);

    wmma::fragment<wmma::accumulator, 16, 16, 16, float> acc0, acc1, acc2, acc3;
    wmma::fill_fragment(acc0, 0.f);
    wmma::fill_fragment(acc1, 0.f);
    wmma::fill_fragment(acc2, 0.f);
    wmma::fill_fragment(acc3, 0.f);

    for (int kc = 0; kc < 4; kc++) {
        int k0 = kc * 64;
        // stage W chunk: 64 k-rows x 64 n-cols, hi + lo (512 uint4 each)
        for (int v = tid; v < 512; v += 256) {
            int r = v >> 3, c = v & 7;
            ((uint4*)sBhi)[v] =
                *((const uint4*)(Whi + (size_t)(k0 + r) * HID + n0) + c);
            ((uint4*)sBlo)[v] =
                *((const uint4*)(Wlo + (size_t)(k0 + r) * HID + n0) + c);
        }
        __syncthreads();

        if (valid) {
#pragma unroll
            for (int ks = 0; ks < 4; ks++) {
                int k = k0 + ks * 16;
                wmma::fragment<wmma::matrix_a, 16, 16, 16, __nv_bfloat16,
                               wmma::row_major> ah, al;
                wmma::load_matrix_sync(
                    ah, (const __nv_bfloat16*)Ahi + (size_t)m0 * HID + k, HID);
                wmma::load_matrix_sync(
                    al, (const __nv_bfloat16*)Alo + (size_t)m0 * HID + k, HID);
                NFRAG(acc0, 0);
                NFRAG(acc1, 1);
                NFRAG(acc2, 2);
                NFRAG(acc3, 3);
            }
        }
        __syncthreads();
    }

    if (valid) {
        float* cp = C + (size_t)m0 * HID + n0;
        wmma::store_matrix_sync(cp,      acc0, HID, wmma::mem_row_major);
        wmma::store_matrix_sync(cp + 16, acc1, HID, wmma::mem_row_major);
        wmma::store_matrix_sync(cp + 32, acc2, HID, wmma::mem_row_major);
        wmma::store_matrix_sync(cp + 48, acc3, HID, wmma::mem_row_major);
    }
}

// ---------------- attention: warp per destination node ---------------------
__global__ void attn_kernel(int n) {
    int gw = (blockIdx.x * blockDim.x + threadIdx.x) >> 5;
    if (gw >= n) return;
    int lane = threadIdx.x & 31;

    const float* qr = g_Q + (size_t)gw * HID + lane * 8;
    float4 q0 = *(const float4*)qr;
    float4 q1 = *(const float4*)(qr + 4);

    int beg = g_rowoff[gw];
    int end = g_rowoff[gw + 1];

    float m = -INFINITY;
    float den = 0.f;
    float a0 = 0.f, a1 = 0.f, a2 = 0.f, a3 = 0.f;
    float a4 = 0.f, a5 = 0.f, a6 = 0.f, a7 = 0.f;

    for (int e = beg; e < end; ++e) {
        int s = g_csrc[e];
        const float* kr = g_K + (size_t)s * HID + lane * 8;
        const float* vr = g_V + (size_t)s * HID + lane * 8;
        float4 k0 = *(const float4*)kr;
        float4 k1 = *(const float4*)(kr + 4);
        float4 v0 = *(const float4*)vr;
        float4 v1 = *(const float4*)(vr + 4);

        float p = q0.x * k0.x + q0.y * k0.y + q0.z * k0.z + q0.w * k0.w +
                  q1.x * k1.x + q1.y * k1.y + q1.z * k1.z + q1.w * k1.w;
        p += __shfl_xor_sync(0xffffffffu, p, 1);
        p += __shfl_xor_sync(0xffffffffu, p, 2);
        float sc = p * 0.17677669529663687f;   // 1/sqrt(32)

        float nm = fmaxf(m, sc);
        float cf = __expf(m - nm);
        float pf = __expf(sc - nm);
        den = den * cf + pf;
        a0 = a0 * cf + pf * v0.x;
        a1 = a1 * cf + pf * v0.y;
        a2 = a2 * cf + pf * v0.z;
        a3 = a3 * cf + pf * v0.w;
        a4 = a4 * cf + pf * v1.x;
        a5 = a5 * cf + pf * v1.y;
        a6 = a6 * cf + pf * v1.z;
        a7 = a7 * cf + pf * v1.w;
        m = nm;
    }

    float inv = (den > 0.f) ? 1.f / den : 0.f;
    float* o = g_attn + (size_t)gw * HID + lane * 8;
    *(float4*)o = make_float4(a0 * inv, a1 * inv, a2 * inv, a3 * inv);
    *(float4*)(o + 4) = make_float4(a4 * inv, a5 * inv, a6 * inv, a7 * inv);
}

// ---------------- GraphNorm stats + apply + GELU (h = raw + bias + x) ------
__global__ void stats_kernel(const float* __restrict__ bias,
                             const float* __restrict__ x, int n) {
    int c = threadIdx.x;
    float b = bias[c];
    float s = 0.f, s2 = 0.f;
    for (int r = blockIdx.x; r < n; r += gridDim.x) {
        float v = g_h[(size_t)r * HID + c] + b + x[(size_t)r * HID + c];
        s += v;
        s2 += v * v;
    }
    atomicAdd(&g_colsum[c], s);
    atomicAdd(&g_colsq[c], s2);
}

__global__ void norm_gelu_kernel(const float* __restrict__ gw,
                                 const float* __restrict__ gb,
                                 const float* __restrict__ gms,
                                 const float* __restrict__ bias,
                                 const float* __restrict__ x,
                                 float* __restrict__ out, int n) {
    int c = threadIdx.x;
    float invn = 1.f / (float)n;
    float mean = g_colsum[c] * invn;
    float ex2  = g_colsq[c] * invn;
    float s = gms[c];
    float var = ex2 - 2.f * s * mean * mean + s * s * mean * mean;
    float rstd = rsqrtf(var + 1e-5f);
    float w = gw[c] * rstd;
    float bb = gb[c];
    float off = s * mean;
    float bc = bias[c];
    for (int r = blockIdx.x; r < n; r += gridDim.x) {
        float h = g_h[(size_t)r * HID + c] + bc + x[(size_t)r * HID + c];
        float o = (h - off) * w + bb;
        out[(size_t)r * HID + c] = 0.5f * o * (1.f + erff(o * 0.70710678118654752f));
    }
}

// ---------------- launch ----------------------------------------------------
extern "C" void kernel_launch(void* const* d_in, const int* in_sizes, int n_in,
                              void* d_out, int out_size) {
    const float* x     = (const float*)d_in[0];
    const float* WQ    = (const float*)d_in[1];
    const float* WK    = (const float*)d_in[2];
    const float* WV    = (const float*)d_in[3];
    const float* W_out = (const float*)d_in[4];
    const float* b_out = (const float*)d_in[5];
    const float* gnw   = (const float*)d_in[6];
    const float* gnb   = (const float*)d_in[7];
    const float* gms   = (const float*)d_in[8];
    const int*   ei    = (const int*)d_in[9];

    int n = in_sizes[0] / HID;
    int e = in_sizes[9] / 2;
    if (n > NMAX || e > EMAX) return;

    const int* src = ei;
    const int* dst = ei + e;

    // CSR build
    zero_kernel<<<(n + 256) / 256, 256>>>(n);
    count_kernel<<<(e + 255) / 256, 256>>>(dst, e);
    int nb = (n + 1023) / 1024;
    scanA<<<nb, 1024>>>(n);
    scanB<<<1, 64>>>(nb);
    scanC<<<(n + 255) / 256, 256>>>(n, e);
    scatter_kernel<<<(e + 255) / 256, 256>>>(src, dst, e);

    // bf16 splits (all device buffers referenced inside device code)
    int t2 = n * HID / 2;
    conv_split<0><<<(t2 + 255) / 256, 256>>>(x, t2);
    conv_w<<<256, 256>>>(WQ, 0);
    conv_w<<<256, 256>>>(WK, 1);
    conv_w<<<256, 256>>>(WV, 2);
    conv_w<<<256, 256>>>(W_out, 3);

    int mt = (n + 127) / 128;

    // QKV projections (WMMA tensor cores)
    dim3 gqkv(4, mt, 3);
    gemm_wmma<0><<<gqkv, 256>>>(n);

    // attention (warp per node)
    attn_kernel<<<(n * 32 + 255) / 256, 256>>>(n);

    // out projection -> g_h raw
    conv_split<1><<<(t2 + 255) / 256, 256>>>(nullptr, t2);
    dim3 gout(4, mt, 1);
    gemm_wmma<1><<<gout, 256>>>(n);

    // GraphNorm + GELU (bias + residual folded in)
    stats_kernel<<<512, 256>>>(b_out, x, n);
    norm_gelu_kernel<<<512, 256>>>(gnw, gnb, gms, b_out, x, (float*)d_out, n);
}